// round 15
// baseline (speedup 1.0000x reference)
#include <cuda_runtime.h>
#include <cuda_bf16.h>
#include <math.h>
#include <cstdint>

// ---------------- problem constants ----------------
#define BATCH   2
#define SEQLEN  512
#define DMODEL  1024
#define DIN     4384          // D_IN_PROJ
#define DINNER  2048
#define CONVD   2304          // CONV_DIM
#define DSTATE  128
#define NHEADS  32
#define HEADD   64
#define NCLS    48
#define NTOK    (BATCH*SEQLEN)   // 1024

// split-pair GEMM: 96 K-chunks of 32; segments selected per chunk
#define NPAD    4480
#define KTILE   32
#define NKT     96
#define SMSTRIDE 40
#define GSTAGE_B 20480
#define GEMM_SMEM (3 * GSTAGE_B)

// classifier tiling
#define CLS_TOK   8
#define CLS_KT    128
#define CLS_WPAD  52

// ---------------- device scratch ----------------
__device__ float g_zx   [(size_t)NTOK * DIN];
__device__ float g_xbc  [(size_t)NTOK * CONVD];
__device__ float g_dts  [(size_t)NTOK * NHEADS];
__device__ float g_dAs  [(size_t)NTOK * NHEADS];
__device__ float g_y0   [(size_t)NTOK * DINNER];
__device__ float g_y1   [(size_t)NTOK * DINNER];
__device__ float g_hn   [(size_t)NTOK * DINNER];
__device__ __nv_bfloat16 g_Ahi[(size_t)NTOK * DMODEL];
__device__ __nv_bfloat16 g_Alo[(size_t)NTOK * DMODEL];
__device__ __nv_bfloat16 g_Bhi[(size_t)NPAD * DMODEL];
__device__ __nv_bfloat16 g_Blo[(size_t)NPAD * DMODEL];

// ================= helpers =================
__device__ __forceinline__ uint32_t smem_u32(const void* p) {
    uint32_t a;
    asm("{ .reg .u64 t; cvta.to.shared.u64 t, %1; cvt.u32.u64 %0, t; }"
        : "=r"(a) : "l"(p));
    return a;
}
__device__ __forceinline__ void ldsm4(uint32_t& r0, uint32_t& r1,
                                      uint32_t& r2, uint32_t& r3, uint32_t addr) {
    asm volatile("ldmatrix.sync.aligned.m8n8.x4.shared.b16 {%0,%1,%2,%3}, [%4];"
                 : "=r"(r0), "=r"(r1), "=r"(r2), "=r"(r3) : "r"(addr));
}
__device__ __forceinline__ void mma16816(float* c, const uint32_t* a,
                                         uint32_t b0, uint32_t b1) {
    asm volatile(
        "mma.sync.aligned.m16n8k16.row.col.f32.bf16.bf16.f32 "
        "{%0,%1,%2,%3}, {%4,%5,%6,%7}, {%8,%9}, {%0,%1,%2,%3};"
        : "+f"(c[0]), "+f"(c[1]), "+f"(c[2]), "+f"(c[3])
        : "r"(a[0]), "r"(a[1]), "r"(a[2]), "r"(a[3]), "r"(b0), "r"(b1));
}
__device__ __forceinline__ void cpasync16(uint32_t s, const void* g) {
    asm volatile("cp.async.cg.shared.global [%0], [%1], 16;" :: "r"(s), "l"(g));
}
#define CP_COMMIT() asm volatile("cp.async.commit_group;" ::: "memory")
#define CP_WAIT1()  asm volatile("cp.async.wait_group 1;"  ::: "memory")

__device__ __forceinline__ float siluf(float v) {
    return v / (1.f + expf(-v));
}

// ================= Kernel 1: hi/lo bf16 split conversion =================
__global__ void __launch_bounds__(256) k_cvt(const float* __restrict__ A,
                                             const float* __restrict__ W)
{
    int t = threadIdx.x;
    if (blockIdx.x < 1024) {
        int base = (blockIdx.x * 256 + t) * 4;
        int m = base >> 10, k = base & 1023;
        float4 v = *(const float4*)&A[base];
        __nv_bfloat16 hi[4], lo[4];
        hi[0] = __float2bfloat16(v.x); lo[0] = __float2bfloat16(v.x - __bfloat162float(hi[0]));
        hi[1] = __float2bfloat16(v.y); lo[1] = __float2bfloat16(v.y - __bfloat162float(hi[1]));
        hi[2] = __float2bfloat16(v.z); lo[2] = __float2bfloat16(v.z - __bfloat162float(hi[2]));
        hi[3] = __float2bfloat16(v.w); lo[3] = __float2bfloat16(v.w - __bfloat162float(hi[3]));
        size_t o = (size_t)m * DMODEL + k;
        *(uint2*)&g_Ahi[o] = *(uint2*)hi;
        *(uint2*)&g_Alo[o] = *(uint2*)lo;
    } else {
        __shared__ float tile[64][65];
        int bid2 = blockIdx.x - 1024;
        int k0 = (bid2 & 15) * 64;
        int n0 = (bid2 >> 4) * 64;
#pragma unroll
        for (int i = 0; i < 16; ++i) {
            int u = t + i * 256;
            int kr = u >> 6, nn = u & 63;
            int n = n0 + nn;
            tile[kr][nn] = (n < DIN) ? W[(size_t)(k0 + kr) * DIN + n] : 0.f;
        }
        __syncthreads();
#pragma unroll
        for (int i = 0; i < 2; ++i) {
            int u = t + i * 256;
            int nr = u >> 3, kb = (u & 7) * 8;
            __nv_bfloat16 hi[8], lo[8];
#pragma unroll
            for (int j = 0; j < 8; ++j) {
                float v = tile[kb + j][nr];
                hi[j] = __float2bfloat16(v);
                lo[j] = __float2bfloat16(v - __bfloat162float(hi[j]));
            }
            size_t o = (size_t)(n0 + nr) * DMODEL + k0 + kb;
            *(uint4*)&g_Bhi[o] = *(uint4*)hi;
            *(uint4*)&g_Blo[o] = *(uint4*)lo;
        }
    }
}

// ================= Kernel 2: bf16 HMMA GEMM (cp.async 3-stage) ===========
#define GEMM_ISSUE(cc, st) do {                                              \
    uint32_t sb = smbase + (st) * GSTAGE_B;                                  \
    int kk = ((cc) & 31) * KTILE;                                            \
    const __nv_bfloat16* Ap = (((cc) < 64) ? g_Ahi : g_Alo) + aoff + kk;     \
    const __nv_bfloat16* Bp = ((((cc) >> 5) == 1) ? g_Blo : g_Bhi) + boff + kk; \
    cpasync16(sb + sA0, Ap);                                                 \
    cpasync16(sb + sA1, Ap + half64);                                        \
    cpasync16(sb + sB0, Bp);                                                 \
    cpasync16(sb + sB1, Bp + half64);                                        \
} while (0)

__global__ void __launch_bounds__(256, 2) k_gemm_mma(int coltile0)
{
    extern __shared__ char dsm[];
    const uint32_t smbase = smem_u32(dsm);

    const int tid = threadIdx.x;
    const int wid = tid >> 5, lid = tid & 31;
    const int row0 = blockIdx.y * 128;
    const int col0 = (coltile0 + blockIdx.x) * 128;
    const int wm = wid >> 1;
    const int wn = wid & 1;

    const int grow = tid >> 2;
    const int gseg = tid & 3;
    const size_t aoff = (size_t)(row0 + grow) * DMODEL + gseg * 8;
    const size_t boff = (size_t)(col0 + grow) * DMODEL + gseg * 8;
    const size_t half64 = (size_t)64 * DMODEL;

    const uint32_t sA0 = grow * (SMSTRIDE * 2) + gseg * 16;
    const uint32_t sA1 = sA0 + 64 * (SMSTRIDE * 2);
    const uint32_t sB0 = sA0 + 10240;
    const uint32_t sB1 = sA1 + 10240;

    float acc[2][8][4];
#pragma unroll
    for (int i = 0; i < 2; ++i)
#pragma unroll
        for (int j = 0; j < 8; ++j)
#pragma unroll
            for (int v = 0; v < 4; ++v) acc[i][j][v] = 0.f;

    const int lrow = lid & 15;
    const int lk   = (lid >> 4) * 16;

    GEMM_ISSUE(0, 0); CP_COMMIT();
    GEMM_ISSUE(1, 1); CP_COMMIT();

    int stage = 0;
    for (int c = 0; c < NKT; ++c) {
        CP_WAIT1();
        __syncthreads();
        if (c + 2 < NKT) {
            int st2 = stage + 2; if (st2 >= 3) st2 -= 3;
            GEMM_ISSUE(c + 2, st2);
        }
        CP_COMMIT();

        uint32_t Ab = smbase + stage * GSTAGE_B;
        uint32_t Bb = Ab + 10240;
#pragma unroll
        for (int s = 0; s < 2; ++s) {
            uint32_t a[2][4];
#pragma unroll
            for (int mi = 0; mi < 2; ++mi) {
                uint32_t addr = Ab + (wm * 32 + mi * 16 + lrow) * (SMSTRIDE * 2)
                              + s * 32 + lk;
                ldsm4(a[mi][0], a[mi][1], a[mi][2], a[mi][3], addr);
            }
            uint32_t b[4][4];
#pragma unroll
            for (int nj = 0; nj < 4; ++nj) {
                uint32_t addr = Bb + (wn * 64 + nj * 16 + lrow) * (SMSTRIDE * 2)
                              + s * 32 + lk;
                ldsm4(b[nj][0], b[nj][1], b[nj][2], b[nj][3], addr);
            }
#pragma unroll
            for (int mi = 0; mi < 2; ++mi)
#pragma unroll
                for (int nj = 0; nj < 8; ++nj) {
                    int qq = nj >> 1, rr = nj & 1;
                    mma16816(acc[mi][nj], a[mi], b[qq][rr], b[qq][rr + 2]);
                }
        }
        if (++stage >= 3) stage = 0;
    }

    const int crow = lid >> 2;
    const int ccol = (lid & 3) * 2;
#pragma unroll
    for (int mi = 0; mi < 2; ++mi) {
#pragma unroll
        for (int nj = 0; nj < 8; ++nj) {
            int col = col0 + wn * 64 + nj * 8 + ccol;
            if (col < DIN) {
                int r = row0 + wm * 32 + mi * 16 + crow;
                *(float2*)&g_zx[(size_t)r * DIN + col] =
                    make_float2(acc[mi][nj][0], acc[mi][nj][1]);
                *(float2*)&g_zx[(size_t)(r + 8) * DIN + col] =
                    make_float2(acc[mi][nj][2], acc[mi][nj][3]);
            }
        }
    }
}

// ================= Kernel 3: conv + SiLU (full, feeds gatenorm only) =====
__global__ void __launch_bounds__(256) k_conv(const float* __restrict__ cw,
                                              const float* __restrict__ cb,
                                              const float* __restrict__ dtb,
                                              const float* __restrict__ Alog)
{
    const int PER = CONVD;
    int idx = blockIdx.x * 256 + threadIdx.x;
    if (idx >= NTOK * PER) return;
    int c      = idx % PER;
    int tokidx = idx / PER;
    int l      = tokidx & (SEQLEN - 1);

    float acc = cb[c];
#pragma unroll
    for (int j = 0; j < 4; ++j) {
        int lj = l - 3 + j;
        if (lj >= 0)
            acc = fmaf(cw[c * 4 + j],
                       g_zx[(size_t)(tokidx - 3 + j) * DIN + DINNER + c], acc);
    }
    acc = acc / (1.f + expf(-acc));
    g_xbc[(size_t)tokidx * CONVD + c] = acc;
    (void)dtb; (void)Alog;
}

// ================= Kernel 4: fused conv+scan (monolithic, inline conv) ===
__global__ void __launch_bounds__(256, 1) k_scan(const float* __restrict__ cw,
                                                 const float* __restrict__ cb,
                                                 const float* __restrict__ dtb,
                                                 const float* __restrict__ Alog)
{
    int blk  = blockIdx.x;
    int b    = blk >> 6;
    int rem  = blk & 63;
    int h    = rem >> 1;
    int nh   = rem & 1;
    int tid  = threadIdx.x;
    int pp = tid >> 3;
    int q  = tid & 7;
    int p0 = pp * 2;

    __shared__ __align__(16) float xs[2][8][64];
    __shared__ __align__(16) float Bh[2][8][64];
    __shared__ __align__(16) float Ch[2][8][64];
    __shared__ float sdt[SEQLEN], sdA[SEQLEN];

    const float* zxb = g_zx + (size_t)(b * SEQLEN) * DIN;

    // inline dt/dA from raw gemm output
    {
        float negA = -expf(Alog[h]);
        float bias = dtb[h];
        for (int t = tid; t < SEQLEN; t += 256) {
            float raw = zxb[(size_t)t * DIN + DINNER + CONVD + h] + bias;
            float sp  = (raw > 15.f) ? raw : log1pf(expf(raw));
            sdt[t] = sp;
            sdA[t] = expf(sp * negA);
        }
    }

    float s0[8], s1[8];
#pragma unroll
    for (int j = 0; j < 8; ++j) { s0[j] = 0.f; s1[j] = 0.f; }

    float* yout = nh ? g_y1 : g_y0;

    // stager channel (xbc space): x / B / C
    int cx = -1;
    if (tid < 64)        cx = h * HEADD + tid;
    else if (tid < 128)  cx = DINNER + nh * 64 + (tid - 64);
    else if (tid < 192)  cx = DINNER + DSTATE + nh * 64 + (tid - 128);
    bool stager = (cx >= 0);

    float w0 = 0.f, w1 = 0.f, w2 = 0.f, w3 = 0.f, bbv = 0.f;
    const float* zcol = nullptr;
    float raw[11];
    if (stager) {
        w0 = cw[cx * 4 + 0]; w1 = cw[cx * 4 + 1];
        w2 = cw[cx * 4 + 2]; w3 = cw[cx * 4 + 3];
        bbv = cb[cx];
        zcol = zxb + (DINNER + cx);
        // group 0 raw: t = -3..7
#pragma unroll
        for (int i = 0; i < 11; ++i) {
            int t = -3 + i;
            raw[i] = (t >= 0) ? zcol[(size_t)t * DIN] : 0.f;
        }
    }

    float* youtbase = yout + ((size_t)(b * SEQLEN) * NHEADS + h) * HEADD + p0;

    for (int tg = 0; tg < SEQLEN / 8; ++tg) {
        int set = tg & 1;
        if (stager) {
            float cv[8];
#pragma unroll
            for (int u = 0; u < 8; ++u) {
                float a = bbv;
                a = fmaf(w0, raw[u],     a);
                a = fmaf(w1, raw[u + 1], a);
                a = fmaf(w2, raw[u + 2], a);
                a = fmaf(w3, raw[u + 3], a);
                cv[u] = siluf(a);
            }
            if (tid < 64) {
#pragma unroll
                for (int j = 0; j < 8; ++j) xs[set][j][tid] = cv[j];
            } else if (tid < 128) {
#pragma unroll
                for (int j = 0; j < 8; ++j) Bh[set][j][tid - 64] = cv[j];
            } else {
#pragma unroll
                for (int j = 0; j < 8; ++j) Ch[set][j][tid - 128] = cv[j];
            }
        }
        __syncthreads();
        if (stager && tg + 1 < SEQLEN / 8) {
            int t0n = (tg + 1) * 8 - 3;     // >= 5
#pragma unroll
            for (int i = 0; i < 11; ++i)
                raw[i] = zcol[(size_t)(t0n + i) * DIN];
        }

#pragma unroll
        for (int u = 0; u < 8; ++u) {
            int t = tg * 8 + u;
            float dtv = sdt[t], dAv = sdA[t];
            float2 xv = *(const float2*)&xs[set][u][p0];
            float xd0 = xv.x * dtv, xd1 = xv.y * dtv;
            float4 Bv0 = *(const float4*)&Bh[set][u][q * 8];
            float4 Bv1 = *(const float4*)&Bh[set][u][q * 8 + 4];
            float4 Cv0 = *(const float4*)&Ch[set][u][q * 8];
            float4 Cv1 = *(const float4*)&Ch[set][u][q * 8 + 4];

            float y0 = 0.f, y1 = 0.f;
#define STEPN(j, bv, cv)                                           \
            s0[j] = fmaf(s0[j], dAv, xd0 * (bv));                  \
            y0    = fmaf(s0[j], (cv), y0);                         \
            s1[j] = fmaf(s1[j], dAv, xd1 * (bv));                  \
            y1    = fmaf(s1[j], (cv), y1);
            STEPN(0, Bv0.x, Cv0.x)
            STEPN(1, Bv0.y, Cv0.y)
            STEPN(2, Bv0.z, Cv0.z)
            STEPN(3, Bv0.w, Cv0.w)
            STEPN(4, Bv1.x, Cv1.x)
            STEPN(5, Bv1.y, Cv1.y)
            STEPN(6, Bv1.z, Cv1.z)
            STEPN(7, Bv1.w, Cv1.w)
#undef STEPN
            y0 += __shfl_xor_sync(0xffffffffu, y0, 1);
            y1 += __shfl_xor_sync(0xffffffffu, y1, 1);
            y0 += __shfl_xor_sync(0xffffffffu, y0, 2);
            y1 += __shfl_xor_sync(0xffffffffu, y1, 2);
            y0 += __shfl_xor_sync(0xffffffffu, y0, 4);
            y1 += __shfl_xor_sync(0xffffffffu, y1, 4);
            if (q == 0)
                *(float2*)&youtbase[(size_t)t * DINNER] = make_float2(y0, y1);
        }
    }
}

// ================= Kernel 5: gating + RMSNorm ============================
__global__ void __launch_bounds__(256) k_gatenorm(const float* __restrict__ Dv,
                                                  const float* __restrict__ nw)
{
    int tok = blockIdx.x;
    int tid = threadIdx.x;
    __shared__ float gsh[DINNER];
    __shared__ float red[8];
    __shared__ float scale_s;

    float ss = 0.f;
#pragma unroll
    for (int k = 0; k < 8; ++k) {
        int i = tid + k * 256;
        int h = i >> 6;
        float x  = g_xbc[(size_t)tok * CONVD + i];
        float yv = g_y0[(size_t)tok * DINNER + i] + g_y1[(size_t)tok * DINNER + i]
                 + Dv[h] * x;
        float z  = g_zx[(size_t)tok * DIN + i];
        float g  = yv * (z / (1.f + expf(-z)));
        gsh[i] = g;
        ss = fmaf(g, g, ss);
    }
#pragma unroll
    for (int o = 16; o; o >>= 1) ss += __shfl_xor_sync(0xffffffffu, ss, o);
    if ((tid & 31) == 0) red[tid >> 5] = ss;
    __syncthreads();
    if (tid == 0) {
        float tot = 0.f;
#pragma unroll
        for (int w = 0; w < 8; ++w) tot += red[w];
        scale_s = rsqrtf(tot / (float)DINNER + 1e-5f);
    }
    __syncthreads();
    float sc = scale_s;
#pragma unroll
    for (int k = 0; k < 8; ++k) {
        int i = tid + k * 256;
        g_hn[(size_t)tok * DINNER + i] = gsh[i] * sc * nw[i];
    }
}

// ================= Kernel 6: classifier GEMM (warp K-split) ==============
__global__ void __launch_bounds__(256) k_cls(const float* __restrict__ Wc,
                                             const float* __restrict__ bc,
                                             float* __restrict__ out)
{
    __shared__ float Ws[CLS_KT * CLS_WPAD];
    __shared__ float Hs[CLS_TOK * CLS_KT];

    const int tok0 = blockIdx.x * CLS_TOK;
    const int tid  = threadIdx.x;
    const int tg = tid >> 7;
    const int qg = (tid >> 5) & 3;
    const int kg = tid & 31;

    float acc[4][12];
#pragma unroll
    for (int t = 0; t < 4; ++t)
#pragma unroll
        for (int j = 0; j < 12; ++j) acc[t][j] = 0.f;

    for (int k0 = 0; k0 < DINNER; k0 += CLS_KT) {
#pragma unroll
        for (int r = 0; r < 24; ++r) {
            int idx = tid + r * 256;
            int kk = idx / 48, c = idx - kk * 48;
            Ws[kk * CLS_WPAD + c] = Wc[(size_t)(k0 + kk) * NCLS + c];
        }
#pragma unroll
        for (int r = 0; r < 4; ++r) {
            int idx = tid + r * 256;
            int tt = idx >> 7, kk = idx & 127;
            Hs[tt * CLS_KT + kk] = g_hn[(size_t)(tok0 + tt) * DINNER + k0 + kk];
        }
        __syncthreads();

#pragma unroll
        for (int i = 0; i < 4; ++i) {
            int kk = i * 32 + kg;
            float hv[4];
#pragma unroll
            for (int t = 0; t < 4; ++t)
                hv[t] = Hs[(tg * 4 + t) * CLS_KT + kk];
            const float* wr = &Ws[kk * CLS_WPAD + qg * 12];
            float4 w0 = *(const float4*)(wr);
            float4 w1 = *(const float4*)(wr + 4);
            float4 w2 = *(const float4*)(wr + 8);
#pragma unroll
            for (int t = 0; t < 4; ++t) {
                acc[t][0]  = fmaf(hv[t], w0.x, acc[t][0]);
                acc[t][1]  = fmaf(hv[t], w0.y, acc[t][1]);
                acc[t][2]  = fmaf(hv[t], w0.z, acc[t][2]);
                acc[t][3]  = fmaf(hv[t], w0.w, acc[t][3]);
                acc[t][4]  = fmaf(hv[t], w1.x, acc[t][4]);
                acc[t][5]  = fmaf(hv[t], w1.y, acc[t][5]);
                acc[t][6]  = fmaf(hv[t], w1.z, acc[t][6]);
                acc[t][7]  = fmaf(hv[t], w1.w, acc[t][7]);
                acc[t][8]  = fmaf(hv[t], w2.x, acc[t][8]);
                acc[t][9]  = fmaf(hv[t], w2.y, acc[t][9]);
                acc[t][10] = fmaf(hv[t], w2.z, acc[t][10]);
                acc[t][11] = fmaf(hv[t], w2.w, acc[t][11]);
            }
        }
        __syncthreads();
    }

#pragma unroll
    for (int offw = 16; offw; offw >>= 1)
#pragma unroll
        for (int t = 0; t < 4; ++t)
#pragma unroll
            for (int j = 0; j < 12; ++j)
                acc[t][j] += __shfl_down_sync(0xffffffffu, acc[t][j], offw);

    if (kg == 0) {
#pragma unroll
        for (int t = 0; t < 4; ++t) {
            int tok = tok0 + tg * 4 + t;
            float* op = &out[(size_t)tok * NCLS + qg * 12];
#pragma unroll
            for (int j = 0; j < 12; ++j)
                op[j] = acc[t][j] + bc[qg * 12 + j];
        }
    }
}

// ================= launcher: conv + z-GEMM both hide under fused scan ====
extern "C" void kernel_launch(void* const* d_in, const int* in_sizes, int n_in,
                              void* d_out, int out_size)
{
    const float* inputs  = (const float*)d_in[0];
    const float* W_in    = (const float*)d_in[1];
    const float* conv_w  = (const float*)d_in[2];
    const float* conv_b  = (const float*)d_in[3];
    const float* dt_bias = (const float*)d_in[4];
    const float* A_log   = (const float*)d_in[5];
    const float* Dv      = (const float*)d_in[6];
    const float* norm_w  = (const float*)d_in[7];
    const float* W_cls   = (const float*)d_in[9];
    const float* b_cls   = (const float*)d_in[10];
    float* out = (float*)d_out;

    (void)in_sizes; (void)n_in; (void)out_size;

    static cudaStream_t s2 = nullptr;
    static cudaEvent_t ev1 = nullptr, ev2 = nullptr;
    static bool init_done = false;
    if (!init_done) {
        cudaFuncSetAttribute(k_gemm_mma,
                             cudaFuncAttributeMaxDynamicSharedMemorySize,
                             GEMM_SMEM);
        int prio_lo = 0, prio_hi = 0;
        cudaDeviceGetStreamPriorityRange(&prio_lo, &prio_hi);
        cudaStreamCreateWithPriority(&s2, cudaStreamNonBlocking, prio_lo);
        cudaEventCreateWithFlags(&ev1, cudaEventDisableTiming);
        cudaEventCreateWithFlags(&ev2, cudaEventDisableTiming);
        init_done = true;
    }

    // stream 0: conversions, then xBC/dt column tiles of the GEMM
    k_cvt<<<1024 + 1120, 256>>>(inputs, W_in);
    {
        dim3 grid(19, NTOK / 128);           // col tiles 16..34 (cols 2048..4479)
        k_gemm_mma<<<grid, 256, GEMM_SMEM>>>(16);
    }
    // fork: side stream does full conv (for gatenorm) + z-column GEMM,
    // both hiding under the fused scan on stream 0.
    cudaEventRecord(ev1, 0);
    cudaStreamWaitEvent(s2, ev1, 0);
    {
        int tot = NTOK * CONVD;
        k_conv<<<(tot + 255) / 256, 256, 0, s2>>>(conv_w, conv_b, dt_bias, A_log);
    }
    {
        dim3 grid(16, NTOK / 128);           // col tiles 0..15 (z, cols 0..2047)
        k_gemm_mma<<<grid, 256, GEMM_SMEM, s2>>>(0);
    }
    cudaEventRecord(ev2, s2);

    // stream 0: fused conv+scan (computes its own conv inputs inline)
    k_scan<<<128, 256>>>(conv_w, conv_b, dt_bias, A_log);

    // join: gatenorm needs z (s2 gemm) and g_xbc (s2 conv)
    cudaStreamWaitEvent(0, ev2, 0);
    k_gatenorm<<<NTOK, 256>>>(Dv, norm_w);
    k_cls<<<NTOK / CLS_TOK, 256>>>(W_cls, b_cls, out);
}

// round 16
// speedup vs baseline: 1.2317x; 1.2317x over previous
#include <cuda_runtime.h>
#include <cuda_bf16.h>
#include <math.h>
#include <cstdint>

// ---------------- problem constants ----------------
#define BATCH   2
#define SEQLEN  512
#define DMODEL  1024
#define DIN     4384          // D_IN_PROJ
#define DINNER  2048
#define CONVD   2304          // CONV_DIM
#define DSTATE  128
#define NHEADS  32
#define HEADD   64
#define NCLS    48
#define NTOK    (BATCH*SEQLEN)   // 1024

// split-pair GEMM: 96 K-chunks of 32; segments selected per chunk
#define NPAD    4480
#define KTILE   32
#define NKT     96
#define SMSTRIDE 40
#define GSTAGE_B 20480
#define GEMM_SMEM (3 * GSTAGE_B)

// fused gatenorm+cls tiling
#define CLS_TOK   8
#define CLS_KT    128
#define CLS_WPAD  52
#define GC_HN_B   (CLS_TOK * DINNER * 4)            // 65536
#define GC_WS_B   (CLS_KT * CLS_WPAD * 4)           // 26624
#define GC_SMEM   (GC_HN_B + GC_WS_B)               // 92160

// ---------------- device scratch ----------------
__device__ float g_zx   [(size_t)NTOK * DIN];
__device__ float g_xbc  [(size_t)NTOK * CONVD];
__device__ float g_dts  [(size_t)NTOK * NHEADS];
__device__ float g_dAs  [(size_t)NTOK * NHEADS];
__device__ float g_y0   [(size_t)NTOK * DINNER];
__device__ float g_y1   [(size_t)NTOK * DINNER];
__device__ __nv_bfloat16 g_Ahi[(size_t)NTOK * DMODEL];
__device__ __nv_bfloat16 g_Alo[(size_t)NTOK * DMODEL];
__device__ __nv_bfloat16 g_Bhi[(size_t)NPAD * DMODEL];
__device__ __nv_bfloat16 g_Blo[(size_t)NPAD * DMODEL];

// ================= helpers =================
__device__ __forceinline__ uint32_t smem_u32(const void* p) {
    uint32_t a;
    asm("{ .reg .u64 t; cvta.to.shared.u64 t, %1; cvt.u32.u64 %0, t; }"
        : "=r"(a) : "l"(p));
    return a;
}
__device__ __forceinline__ void ldsm4(uint32_t& r0, uint32_t& r1,
                                      uint32_t& r2, uint32_t& r3, uint32_t addr) {
    asm volatile("ldmatrix.sync.aligned.m8n8.x4.shared.b16 {%0,%1,%2,%3}, [%4];"
                 : "=r"(r0), "=r"(r1), "=r"(r2), "=r"(r3) : "r"(addr));
}
__device__ __forceinline__ void mma16816(float* c, const uint32_t* a,
                                         uint32_t b0, uint32_t b1) {
    asm volatile(
        "mma.sync.aligned.m16n8k16.row.col.f32.bf16.bf16.f32 "
        "{%0,%1,%2,%3}, {%4,%5,%6,%7}, {%8,%9}, {%0,%1,%2,%3};"
        : "+f"(c[0]), "+f"(c[1]), "+f"(c[2]), "+f"(c[3])
        : "r"(a[0]), "r"(a[1]), "r"(a[2]), "r"(a[3]), "r"(b0), "r"(b1));
}
__device__ __forceinline__ void cpasync16(uint32_t s, const void* g) {
    asm volatile("cp.async.cg.shared.global [%0], [%1], 16;" :: "r"(s), "l"(g));
}
#define CP_COMMIT() asm volatile("cp.async.commit_group;" ::: "memory")
#define CP_WAIT1()  asm volatile("cp.async.wait_group 1;"  ::: "memory")

// ================= Kernel 1: hi/lo bf16 split conversion =================
__global__ void __launch_bounds__(256) k_cvt(const float* __restrict__ A,
                                             const float* __restrict__ W)
{
    int t = threadIdx.x;
    if (blockIdx.x < 1024) {
        int base = (blockIdx.x * 256 + t) * 4;
        int m = base >> 10, k = base & 1023;
        float4 v = *(const float4*)&A[base];
        __nv_bfloat16 hi[4], lo[4];
        hi[0] = __float2bfloat16(v.x); lo[0] = __float2bfloat16(v.x - __bfloat162float(hi[0]));
        hi[1] = __float2bfloat16(v.y); lo[1] = __float2bfloat16(v.y - __bfloat162float(hi[1]));
        hi[2] = __float2bfloat16(v.z); lo[2] = __float2bfloat16(v.z - __bfloat162float(hi[2]));
        hi[3] = __float2bfloat16(v.w); lo[3] = __float2bfloat16(v.w - __bfloat162float(hi[3]));
        size_t o = (size_t)m * DMODEL + k;
        *(uint2*)&g_Ahi[o] = *(uint2*)hi;
        *(uint2*)&g_Alo[o] = *(uint2*)lo;
    } else {
        __shared__ float tile[64][65];
        int bid2 = blockIdx.x - 1024;
        int k0 = (bid2 & 15) * 64;
        int n0 = (bid2 >> 4) * 64;
#pragma unroll
        for (int i = 0; i < 16; ++i) {
            int u = t + i * 256;
            int kr = u >> 6, nn = u & 63;
            int n = n0 + nn;
            tile[kr][nn] = (n < DIN) ? W[(size_t)(k0 + kr) * DIN + n] : 0.f;
        }
        __syncthreads();
#pragma unroll
        for (int i = 0; i < 2; ++i) {
            int u = t + i * 256;
            int nr = u >> 3, kb = (u & 7) * 8;
            __nv_bfloat16 hi[8], lo[8];
#pragma unroll
            for (int j = 0; j < 8; ++j) {
                float v = tile[kb + j][nr];
                hi[j] = __float2bfloat16(v);
                lo[j] = __float2bfloat16(v - __bfloat162float(hi[j]));
            }
            size_t o = (size_t)(n0 + nr) * DMODEL + k0 + kb;
            *(uint4*)&g_Bhi[o] = *(uint4*)hi;
            *(uint4*)&g_Blo[o] = *(uint4*)lo;
        }
    }
}

// ================= Kernel 2: bf16 HMMA GEMM (cp.async 3-stage) ===========
#define GEMM_ISSUE(cc, st) do {                                              \
    uint32_t sb = smbase + (st) * GSTAGE_B;                                  \
    int kk = ((cc) & 31) * KTILE;                                            \
    const __nv_bfloat16* Ap = (((cc) < 64) ? g_Ahi : g_Alo) + aoff + kk;     \
    const __nv_bfloat16* Bp = ((((cc) >> 5) == 1) ? g_Blo : g_Bhi) + boff + kk; \
    cpasync16(sb + sA0, Ap);                                                 \
    cpasync16(sb + sA1, Ap + half64);                                        \
    cpasync16(sb + sB0, Bp);                                                 \
    cpasync16(sb + sB1, Bp + half64);                                        \
} while (0)

__global__ void __launch_bounds__(256, 2) k_gemm_mma(int coltile0)
{
    extern __shared__ char dsm[];
    const uint32_t smbase = smem_u32(dsm);

    const int tid = threadIdx.x;
    const int wid = tid >> 5, lid = tid & 31;
    const int row0 = blockIdx.y * 128;
    const int col0 = (coltile0 + blockIdx.x) * 128;
    const int wm = wid >> 1;
    const int wn = wid & 1;

    const int grow = tid >> 2;
    const int gseg = tid & 3;
    const size_t aoff = (size_t)(row0 + grow) * DMODEL + gseg * 8;
    const size_t boff = (size_t)(col0 + grow) * DMODEL + gseg * 8;
    const size_t half64 = (size_t)64 * DMODEL;

    const uint32_t sA0 = grow * (SMSTRIDE * 2) + gseg * 16;
    const uint32_t sA1 = sA0 + 64 * (SMSTRIDE * 2);
    const uint32_t sB0 = sA0 + 10240;
    const uint32_t sB1 = sA1 + 10240;

    float acc[2][8][4];
#pragma unroll
    for (int i = 0; i < 2; ++i)
#pragma unroll
        for (int j = 0; j < 8; ++j)
#pragma unroll
            for (int v = 0; v < 4; ++v) acc[i][j][v] = 0.f;

    const int lrow = lid & 15;
    const int lk   = (lid >> 4) * 16;

    GEMM_ISSUE(0, 0); CP_COMMIT();
    GEMM_ISSUE(1, 1); CP_COMMIT();

    int stage = 0;
    for (int c = 0; c < NKT; ++c) {
        CP_WAIT1();
        __syncthreads();
        if (c + 2 < NKT) {
            int st2 = stage + 2; if (st2 >= 3) st2 -= 3;
            GEMM_ISSUE(c + 2, st2);
        }
        CP_COMMIT();

        uint32_t Ab = smbase + stage * GSTAGE_B;
        uint32_t Bb = Ab + 10240;
#pragma unroll
        for (int s = 0; s < 2; ++s) {
            uint32_t a[2][4];
#pragma unroll
            for (int mi = 0; mi < 2; ++mi) {
                uint32_t addr = Ab + (wm * 32 + mi * 16 + lrow) * (SMSTRIDE * 2)
                              + s * 32 + lk;
                ldsm4(a[mi][0], a[mi][1], a[mi][2], a[mi][3], addr);
            }
            uint32_t b[4][4];
#pragma unroll
            for (int nj = 0; nj < 4; ++nj) {
                uint32_t addr = Bb + (wn * 64 + nj * 16 + lrow) * (SMSTRIDE * 2)
                              + s * 32 + lk;
                ldsm4(b[nj][0], b[nj][1], b[nj][2], b[nj][3], addr);
            }
#pragma unroll
            for (int mi = 0; mi < 2; ++mi)
#pragma unroll
                for (int nj = 0; nj < 8; ++nj) {
                    int qq = nj >> 1, rr = nj & 1;
                    mma16816(acc[mi][nj], a[mi], b[qq][rr], b[qq][rr + 2]);
                }
        }
        if (++stage >= 3) stage = 0;
    }

    const int crow = lid >> 2;
    const int ccol = (lid & 3) * 2;
#pragma unroll
    for (int mi = 0; mi < 2; ++mi) {
#pragma unroll
        for (int nj = 0; nj < 8; ++nj) {
            int col = col0 + wn * 64 + nj * 8 + ccol;
            if (col < DIN) {
                int r = row0 + wm * 32 + mi * 16 + crow;
                *(float2*)&g_zx[(size_t)r * DIN + col] =
                    make_float2(acc[mi][nj][0], acc[mi][nj][1]);
                *(float2*)&g_zx[(size_t)(r + 8) * DIN + col] =
                    make_float2(acc[mi][nj][2], acc[mi][nj][3]);
            }
        }
    }
}

// ================= Kernel 3: conv + SiLU + dt/dA (R12 full) ==============
__global__ void __launch_bounds__(256) k_conv(const float* __restrict__ cw,
                                              const float* __restrict__ cb,
                                              const float* __restrict__ dtb,
                                              const float* __restrict__ Alog)
{
    const int PER = CONVD + NHEADS;
    int idx = blockIdx.x * 256 + threadIdx.x;
    if (idx >= NTOK * PER) return;
    int c      = idx % PER;
    int tokidx = idx / PER;
    int l      = tokidx & (SEQLEN - 1);

    if (c < CONVD) {
        float acc = cb[c];
#pragma unroll
        for (int j = 0; j < 4; ++j) {
            int lj = l - 3 + j;
            if (lj >= 0)
                acc = fmaf(cw[c * 4 + j],
                           g_zx[(size_t)(tokidx - 3 + j) * DIN + DINNER + c], acc);
        }
        acc = acc / (1.f + expf(-acc));
        g_xbc[(size_t)tokidx * CONVD + c] = acc;
    } else {
        int h = c - CONVD;
        float raw = g_zx[(size_t)tokidx * DIN + (DINNER + CONVD) + h] + dtb[h];
        float sp  = (raw > 15.f) ? raw : log1pf(expf(raw));
        g_dts[(size_t)tokidx * NHEADS + h] = sp;
        g_dAs[(size_t)tokidx * NHEADS + h] = expf(sp * (-expf(Alog[h])));
    }
}

// ================= Kernel 4: selective scan (R12 monolithic, FROZEN) =====
__global__ void __launch_bounds__(256, 1) k_scan()
{
    int blk  = blockIdx.x;
    int b    = blk >> 6;
    int rem  = blk & 63;
    int h    = rem >> 1;
    int nh   = rem & 1;
    int tid  = threadIdx.x;
    int pp = tid >> 3;
    int q  = tid & 7;
    int p0 = pp * 2;

    __shared__ __align__(16) float xs[2][8][64];
    __shared__ __align__(16) float Bh[2][8][64];
    __shared__ __align__(16) float Ch[2][8][64];
    __shared__ float sdt[SEQLEN], sdA[SEQLEN];

    for (int t = tid; t < SEQLEN; t += 256) {
        sdt[t] = g_dts[(size_t)(b * SEQLEN + t) * NHEADS + h];
        sdA[t] = g_dAs[(size_t)(b * SEQLEN + t) * NHEADS + h];
    }

    float s0[8], s1[8];
#pragma unroll
    for (int j = 0; j < 8; ++j) { s0[j] = 0.f; s1[j] = 0.f; }

    float* yout = nh ? g_y1 : g_y0;
    const float* base = g_xbc + (size_t)(b * SEQLEN) * CONVD;

    int off = -1;
    if (tid < 64)        off = h * HEADD + tid;
    else if (tid < 128)  off = DINNER + nh * 64 + (tid - 64);
    else if (tid < 192)  off = DINNER + DSTATE + nh * 64 + (tid - 128);
    bool stager = (off >= 0);

    float pre[8];
    if (stager) {
#pragma unroll
        for (int j = 0; j < 8; ++j)
            pre[j] = base[(size_t)j * CONVD + off];
    }

    float* youtbase = yout + ((size_t)(b * SEQLEN) * NHEADS + h) * HEADD + p0;

    for (int tg = 0; tg < SEQLEN / 8; ++tg) {
        int set = tg & 1;
        if (stager) {
            if (tid < 64) {
#pragma unroll
                for (int j = 0; j < 8; ++j) xs[set][j][tid] = pre[j];
            } else if (tid < 128) {
#pragma unroll
                for (int j = 0; j < 8; ++j) Bh[set][j][tid - 64] = pre[j];
            } else {
#pragma unroll
                for (int j = 0; j < 8; ++j) Ch[set][j][tid - 128] = pre[j];
            }
        }
        __syncthreads();
        if (stager && tg + 1 < SEQLEN / 8) {
#pragma unroll
            for (int j = 0; j < 8; ++j)
                pre[j] = base[(size_t)((tg + 1) * 8 + j) * CONVD + off];
        }

#pragma unroll
        for (int u = 0; u < 8; ++u) {
            int t = tg * 8 + u;
            float dtv = sdt[t], dAv = sdA[t];
            float2 xv = *(const float2*)&xs[set][u][p0];
            float xd0 = xv.x * dtv, xd1 = xv.y * dtv;
            float4 Bv0 = *(const float4*)&Bh[set][u][q * 8];
            float4 Bv1 = *(const float4*)&Bh[set][u][q * 8 + 4];
            float4 Cv0 = *(const float4*)&Ch[set][u][q * 8];
            float4 Cv1 = *(const float4*)&Ch[set][u][q * 8 + 4];

            float y0 = 0.f, y1 = 0.f;
#define STEPN(j, bv, cv)                                           \
            s0[j] = fmaf(s0[j], dAv, xd0 * (bv));                  \
            y0    = fmaf(s0[j], (cv), y0);                         \
            s1[j] = fmaf(s1[j], dAv, xd1 * (bv));                  \
            y1    = fmaf(s1[j], (cv), y1);
            STEPN(0, Bv0.x, Cv0.x)
            STEPN(1, Bv0.y, Cv0.y)
            STEPN(2, Bv0.z, Cv0.z)
            STEPN(3, Bv0.w, Cv0.w)
            STEPN(4, Bv1.x, Cv1.x)
            STEPN(5, Bv1.y, Cv1.y)
            STEPN(6, Bv1.z, Cv1.z)
            STEPN(7, Bv1.w, Cv1.w)
#undef STEPN
            y0 += __shfl_xor_sync(0xffffffffu, y0, 1);
            y1 += __shfl_xor_sync(0xffffffffu, y1, 1);
            y0 += __shfl_xor_sync(0xffffffffu, y0, 2);
            y1 += __shfl_xor_sync(0xffffffffu, y1, 2);
            y0 += __shfl_xor_sync(0xffffffffu, y0, 4);
            y1 += __shfl_xor_sync(0xffffffffu, y1, 4);
            if (q == 0)
                *(float2*)&youtbase[(size_t)t * DINNER] = make_float2(y0, y1);
        }
    }
}

// ================= Kernel 5: fused gatenorm + classifier ================
// 128 blocks x 256 thr; block = 8 tokens. Phase A: warp-per-token
// gate+RMSNorm into smem. Phase B: warp-K-split classifier from smem.
__global__ void __launch_bounds__(256) k_gatecls(const float* __restrict__ Dv,
                                                 const float* __restrict__ nw,
                                                 const float* __restrict__ Wc,
                                                 const float* __restrict__ bc,
                                                 float* __restrict__ out)
{
    extern __shared__ char gcs[];
    float* hn_s = (float*)gcs;                       // [8][2048]
    float* Ws   = (float*)(gcs + GC_HN_B);           // [128][52]

    const int tok0 = blockIdx.x * CLS_TOK;
    const int tid  = threadIdx.x;
    const int w    = tid >> 5;          // warp = token (phase A)
    const int lane = tid & 31;

    // ---- Phase A: gate + RMSNorm for token tok0+w ----
    {
        int tok = tok0 + w;
        float* hrow = hn_s + w * DINNER;
        float ss = 0.f;
#pragma unroll
        for (int k = 0; k < 64; ++k) {
            int i = lane + k * 32;
            float x  = g_xbc[(size_t)tok * CONVD + i];
            float yv = g_y0[(size_t)tok * DINNER + i] + g_y1[(size_t)tok * DINNER + i]
                     + Dv[i >> 6] * x;
            float z  = g_zx[(size_t)tok * DIN + i];
            float g  = yv * (z / (1.f + expf(-z)));
            hrow[i] = g;
            ss = fmaf(g, g, ss);
        }
#pragma unroll
        for (int o = 16; o; o >>= 1) ss += __shfl_xor_sync(0xffffffffu, ss, o);
        float sc = rsqrtf(ss / (float)DINNER + 1e-5f);
#pragma unroll
        for (int k = 0; k < 64; ++k) {
            int i = lane + k * 32;
            hrow[i] = hrow[i] * sc * nw[i];
        }
    }
    __syncthreads();

    // ---- Phase B: classifier (warp K-split over resident hn_s) ----
    const int tg = tid >> 7;            // token group (4 tokens)
    const int qg = (tid >> 5) & 3;      // class quad group
    const int kg = tid & 31;            // K slice

    float acc[4][12];
#pragma unroll
    for (int t = 0; t < 4; ++t)
#pragma unroll
        for (int j = 0; j < 12; ++j) acc[t][j] = 0.f;

    for (int k0 = 0; k0 < DINNER; k0 += CLS_KT) {
#pragma unroll
        for (int r = 0; r < 24; ++r) {
            int idx = tid + r * 256;
            int kk = idx / 48, c = idx - kk * 48;
            Ws[kk * CLS_WPAD + c] = Wc[(size_t)(k0 + kk) * NCLS + c];
        }
        __syncthreads();

#pragma unroll
        for (int i = 0; i < 4; ++i) {
            int kk = i * 32 + kg;
            float hv[4];
#pragma unroll
            for (int t = 0; t < 4; ++t)
                hv[t] = hn_s[(tg * 4 + t) * DINNER + k0 + kk];
            const float* wr = &Ws[kk * CLS_WPAD + qg * 12];
            float4 w0 = *(const float4*)(wr);
            float4 w1 = *(const float4*)(wr + 4);
            float4 w2 = *(const float4*)(wr + 8);
#pragma unroll
            for (int t = 0; t < 4; ++t) {
                acc[t][0]  = fmaf(hv[t], w0.x, acc[t][0]);
                acc[t][1]  = fmaf(hv[t], w0.y, acc[t][1]);
                acc[t][2]  = fmaf(hv[t], w0.z, acc[t][2]);
                acc[t][3]  = fmaf(hv[t], w0.w, acc[t][3]);
                acc[t][4]  = fmaf(hv[t], w1.x, acc[t][4]);
                acc[t][5]  = fmaf(hv[t], w1.y, acc[t][5]);
                acc[t][6]  = fmaf(hv[t], w1.z, acc[t][6]);
                acc[t][7]  = fmaf(hv[t], w1.w, acc[t][7]);
                acc[t][8]  = fmaf(hv[t], w2.x, acc[t][8]);
                acc[t][9]  = fmaf(hv[t], w2.y, acc[t][9]);
                acc[t][10] = fmaf(hv[t], w2.z, acc[t][10]);
                acc[t][11] = fmaf(hv[t], w2.w, acc[t][11]);
            }
        }
        __syncthreads();
    }

#pragma unroll
    for (int offw = 16; offw; offw >>= 1)
#pragma unroll
        for (int t = 0; t < 4; ++t)
#pragma unroll
            for (int j = 0; j < 12; ++j)
                acc[t][j] += __shfl_down_sync(0xffffffffu, acc[t][j], offw);

    if (kg == 0) {
#pragma unroll
        for (int t = 0; t < 4; ++t) {
            int tok = tok0 + tg * 4 + t;
            float* op = &out[(size_t)tok * NCLS + qg * 12];
#pragma unroll
            for (int j = 0; j < 12; ++j)
                op[j] = acc[t][j] + bc[qg * 12 + j];
        }
    }
}

// ================= launcher (R14 schedule + fused tail) =================
extern "C" void kernel_launch(void* const* d_in, const int* in_sizes, int n_in,
                              void* d_out, int out_size)
{
    const float* inputs  = (const float*)d_in[0];
    const float* W_in    = (const float*)d_in[1];
    const float* conv_w  = (const float*)d_in[2];
    const float* conv_b  = (const float*)d_in[3];
    const float* dt_bias = (const float*)d_in[4];
    const float* A_log   = (const float*)d_in[5];
    const float* Dv      = (const float*)d_in[6];
    const float* norm_w  = (const float*)d_in[7];
    const float* W_cls   = (const float*)d_in[9];
    const float* b_cls   = (const float*)d_in[10];
    float* out = (float*)d_out;

    (void)in_sizes; (void)n_in; (void)out_size;

    static cudaStream_t s2 = nullptr;
    static cudaEvent_t ev1 = nullptr, ev2 = nullptr;
    static bool init_done = false;
    if (!init_done) {
        cudaFuncSetAttribute(k_gemm_mma,
                             cudaFuncAttributeMaxDynamicSharedMemorySize,
                             GEMM_SMEM);
        cudaFuncSetAttribute(k_gatecls,
                             cudaFuncAttributeMaxDynamicSharedMemorySize,
                             GC_SMEM);
        int prio_lo = 0, prio_hi = 0;
        cudaDeviceGetStreamPriorityRange(&prio_lo, &prio_hi);
        cudaStreamCreateWithPriority(&s2, cudaStreamNonBlocking, prio_lo);
        cudaEventCreateWithFlags(&ev1, cudaEventDisableTiming);
        cudaEventCreateWithFlags(&ev2, cudaEventDisableTiming);
        init_done = true;
    }

    // stream 0: conversions, then xBC/dt column tiles of the GEMM
    k_cvt<<<1024 + 1120, 256>>>(inputs, W_in);
    {
        dim3 grid(19, NTOK / 128);           // col tiles 16..34 (cols 2048..4479)
        k_gemm_mma<<<grid, 256, GEMM_SMEM>>>(16);
    }
    // conv on the critical path (coalesced reads; feeds the scan)
    {
        int tot = NTOK * (CONVD + NHEADS);
        k_conv<<<(tot + 255) / 256, 256>>>(conv_w, conv_b, dt_bias, A_log);
    }
    // fork AFTER conv: z-column GEMM (low priority) hides under the scan
    cudaEventRecord(ev1, 0);
    cudaStreamWaitEvent(s2, ev1, 0);
    {
        dim3 grid(16, NTOK / 128);           // col tiles 0..15 (z, cols 0..2047)
        k_gemm_mma<<<grid, 256, GEMM_SMEM, s2>>>(0);
    }
    cudaEventRecord(ev2, s2);

    // stream 0: scan (frozen R12 body)
    k_scan<<<128, 256>>>();

    // join: fused gatenorm+cls needs z (s2 gemm)
    cudaStreamWaitEvent(0, ev2, 0);
    k_gatecls<<<NTOK / CLS_TOK, 256, GC_SMEM>>>(Dv, norm_w, W_cls, b_cls, out);
}

// round 17
// speedup vs baseline: 1.2743x; 1.0346x over previous
#include <cuda_runtime.h>
#include <cuda_bf16.h>
#include <math.h>
#include <cstdint>

// ---------------- problem constants ----------------
#define BATCH   2
#define SEQLEN  512
#define DMODEL  1024
#define DIN     4384          // D_IN_PROJ
#define DINNER  2048
#define CONVD   2304          // CONV_DIM
#define DSTATE  128
#define NHEADS  32
#define HEADD   64
#define NCLS    48
#define NTOK    (BATCH*SEQLEN)   // 1024

// split-pair GEMM: 96 K-chunks of 32; segments selected per chunk
#define NPAD    4480
#define KTILE   32
#define NKT     96
#define SMSTRIDE 40
#define GSTAGE_B 20480
#define GEMM_SMEM (3 * GSTAGE_B)

// classifier tiling
#define CLS_TOK   8
#define CLS_KT    128
#define CLS_WPAD  52

// ---------------- device scratch ----------------
__device__ float g_zx   [(size_t)NTOK * DIN];
__device__ float g_xbc  [(size_t)NTOK * CONVD];
__device__ float g_dts  [(size_t)NTOK * NHEADS];
__device__ float g_dAs  [(size_t)NTOK * NHEADS];
__device__ float g_y0   [(size_t)NTOK * DINNER];
__device__ float g_y1   [(size_t)NTOK * DINNER];
__device__ float g_hn   [(size_t)NTOK * DINNER];
__device__ __nv_bfloat16 g_Ahi[(size_t)NTOK * DMODEL];
__device__ __nv_bfloat16 g_Alo[(size_t)NTOK * DMODEL];
__device__ __nv_bfloat16 g_Bhi[(size_t)NPAD * DMODEL];
__device__ __nv_bfloat16 g_Blo[(size_t)NPAD * DMODEL];

// ================= helpers =================
__device__ __forceinline__ uint32_t smem_u32(const void* p) {
    uint32_t a;
    asm("{ .reg .u64 t; cvta.to.shared.u64 t, %1; cvt.u32.u64 %0, t; }"
        : "=r"(a) : "l"(p));
    return a;
}
__device__ __forceinline__ void ldsm4(uint32_t& r0, uint32_t& r1,
                                      uint32_t& r2, uint32_t& r3, uint32_t addr) {
    asm volatile("ldmatrix.sync.aligned.m8n8.x4.shared.b16 {%0,%1,%2,%3}, [%4];"
                 : "=r"(r0), "=r"(r1), "=r"(r2), "=r"(r3) : "r"(addr));
}
__device__ __forceinline__ void mma16816(float* c, const uint32_t* a,
                                         uint32_t b0, uint32_t b1) {
    asm volatile(
        "mma.sync.aligned.m16n8k16.row.col.f32.bf16.bf16.f32 "
        "{%0,%1,%2,%3}, {%4,%5,%6,%7}, {%8,%9}, {%0,%1,%2,%3};"
        : "+f"(c[0]), "+f"(c[1]), "+f"(c[2]), "+f"(c[3])
        : "r"(a[0]), "r"(a[1]), "r"(a[2]), "r"(a[3]), "r"(b0), "r"(b1));
}
__device__ __forceinline__ void cpasync16(uint32_t s, const void* g) {
    asm volatile("cp.async.cg.shared.global [%0], [%1], 16;" :: "r"(s), "l"(g));
}
#define CP_COMMIT() asm volatile("cp.async.commit_group;" ::: "memory")
#define CP_WAIT1()  asm volatile("cp.async.wait_group 1;"  ::: "memory")

// ================= Kernel 1: hi/lo bf16 split conversion =================
__global__ void __launch_bounds__(256) k_cvt(const float* __restrict__ A,
                                             const float* __restrict__ W)
{
    int t = threadIdx.x;
    if (blockIdx.x < 1024) {
        int base = (blockIdx.x * 256 + t) * 4;
        int m = base >> 10, k = base & 1023;
        float4 v = *(const float4*)&A[base];
        __nv_bfloat16 hi[4], lo[4];
        hi[0] = __float2bfloat16(v.x); lo[0] = __float2bfloat16(v.x - __bfloat162float(hi[0]));
        hi[1] = __float2bfloat16(v.y); lo[1] = __float2bfloat16(v.y - __bfloat162float(hi[1]));
        hi[2] = __float2bfloat16(v.z); lo[2] = __float2bfloat16(v.z - __bfloat162float(hi[2]));
        hi[3] = __float2bfloat16(v.w); lo[3] = __float2bfloat16(v.w - __bfloat162float(hi[3]));
        size_t o = (size_t)m * DMODEL + k;
        *(uint2*)&g_Ahi[o] = *(uint2*)hi;
        *(uint2*)&g_Alo[o] = *(uint2*)lo;
    } else {
        __shared__ float tile[64][65];
        int bid2 = blockIdx.x - 1024;
        int k0 = (bid2 & 15) * 64;
        int n0 = (bid2 >> 4) * 64;
#pragma unroll
        for (int i = 0; i < 16; ++i) {
            int u = t + i * 256;
            int kr = u >> 6, nn = u & 63;
            int n = n0 + nn;
            tile[kr][nn] = (n < DIN) ? W[(size_t)(k0 + kr) * DIN + n] : 0.f;
        }
        __syncthreads();
#pragma unroll
        for (int i = 0; i < 2; ++i) {
            int u = t + i * 256;
            int nr = u >> 3, kb = (u & 7) * 8;
            __nv_bfloat16 hi[8], lo[8];
#pragma unroll
            for (int j = 0; j < 8; ++j) {
                float v = tile[kb + j][nr];
                hi[j] = __float2bfloat16(v);
                lo[j] = __float2bfloat16(v - __bfloat162float(hi[j]));
            }
            size_t o = (size_t)(n0 + nr) * DMODEL + k0 + kb;
            *(uint4*)&g_Bhi[o] = *(uint4*)hi;
            *(uint4*)&g_Blo[o] = *(uint4*)lo;
        }
    }
}

// ================= Kernel 2: bf16 HMMA GEMM (cp.async 3-stage) ===========
#define GEMM_ISSUE(cc, st) do {                                              \
    uint32_t sb = smbase + (st) * GSTAGE_B;                                  \
    int kk = ((cc) & 31) * KTILE;                                            \
    const __nv_bfloat16* Ap = (((cc) < 64) ? g_Ahi : g_Alo) + aoff + kk;     \
    const __nv_bfloat16* Bp = ((((cc) >> 5) == 1) ? g_Blo : g_Bhi) + boff + kk; \
    cpasync16(sb + sA0, Ap);                                                 \
    cpasync16(sb + sA1, Ap + half64);                                        \
    cpasync16(sb + sB0, Bp);                                                 \
    cpasync16(sb + sB1, Bp + half64);                                        \
} while (0)

__global__ void __launch_bounds__(256, 2) k_gemm_mma(int coltile0)
{
    extern __shared__ char dsm[];
    const uint32_t smbase = smem_u32(dsm);

    const int tid = threadIdx.x;
    const int wid = tid >> 5, lid = tid & 31;
    const int row0 = blockIdx.y * 128;
    const int col0 = (coltile0 + blockIdx.x) * 128;
    const int wm = wid >> 1;
    const int wn = wid & 1;

    const int grow = tid >> 2;
    const int gseg = tid & 3;
    const size_t aoff = (size_t)(row0 + grow) * DMODEL + gseg * 8;
    const size_t boff = (size_t)(col0 + grow) * DMODEL + gseg * 8;
    const size_t half64 = (size_t)64 * DMODEL;

    const uint32_t sA0 = grow * (SMSTRIDE * 2) + gseg * 16;
    const uint32_t sA1 = sA0 + 64 * (SMSTRIDE * 2);
    const uint32_t sB0 = sA0 + 10240;
    const uint32_t sB1 = sA1 + 10240;

    float acc[2][8][4];
#pragma unroll
    for (int i = 0; i < 2; ++i)
#pragma unroll
        for (int j = 0; j < 8; ++j)
#pragma unroll
            for (int v = 0; v < 4; ++v) acc[i][j][v] = 0.f;

    const int lrow = lid & 15;
    const int lk   = (lid >> 4) * 16;

    GEMM_ISSUE(0, 0); CP_COMMIT();
    GEMM_ISSUE(1, 1); CP_COMMIT();

    int stage = 0;
    for (int c = 0; c < NKT; ++c) {
        CP_WAIT1();
        __syncthreads();
        if (c + 2 < NKT) {
            int st2 = stage + 2; if (st2 >= 3) st2 -= 3;
            GEMM_ISSUE(c + 2, st2);
        }
        CP_COMMIT();

        uint32_t Ab = smbase + stage * GSTAGE_B;
        uint32_t Bb = Ab + 10240;
#pragma unroll
        for (int s = 0; s < 2; ++s) {
            uint32_t a[2][4];
#pragma unroll
            for (int mi = 0; mi < 2; ++mi) {
                uint32_t addr = Ab + (wm * 32 + mi * 16 + lrow) * (SMSTRIDE * 2)
                              + s * 32 + lk;
                ldsm4(a[mi][0], a[mi][1], a[mi][2], a[mi][3], addr);
            }
            uint32_t b[4][4];
#pragma unroll
            for (int nj = 0; nj < 4; ++nj) {
                uint32_t addr = Bb + (wn * 64 + nj * 16 + lrow) * (SMSTRIDE * 2)
                              + s * 32 + lk;
                ldsm4(b[nj][0], b[nj][1], b[nj][2], b[nj][3], addr);
            }
#pragma unroll
            for (int mi = 0; mi < 2; ++mi)
#pragma unroll
                for (int nj = 0; nj < 8; ++nj) {
                    int qq = nj >> 1, rr = nj & 1;
                    mma16816(acc[mi][nj], a[mi], b[qq][rr], b[qq][rr + 2]);
                }
        }
        if (++stage >= 3) stage = 0;
    }

    const int crow = lid >> 2;
    const int ccol = (lid & 3) * 2;
#pragma unroll
    for (int mi = 0; mi < 2; ++mi) {
#pragma unroll
        for (int nj = 0; nj < 8; ++nj) {
            int col = col0 + wn * 64 + nj * 8 + ccol;
            if (col < DIN) {
                int r = row0 + wm * 32 + mi * 16 + crow;
                *(float2*)&g_zx[(size_t)r * DIN + col] =
                    make_float2(acc[mi][nj][0], acc[mi][nj][1]);
                *(float2*)&g_zx[(size_t)(r + 8) * DIN + col] =
                    make_float2(acc[mi][nj][2], acc[mi][nj][3]);
            }
        }
    }
}

// ================= Kernel 3: conv + SiLU + dt/dA (R12 full) ==============
__global__ void __launch_bounds__(256) k_conv(const float* __restrict__ cw,
                                              const float* __restrict__ cb,
                                              const float* __restrict__ dtb,
                                              const float* __restrict__ Alog)
{
    const int PER = CONVD + NHEADS;
    int idx = blockIdx.x * 256 + threadIdx.x;
    if (idx >= NTOK * PER) return;
    int c      = idx % PER;
    int tokidx = idx / PER;
    int l      = tokidx & (SEQLEN - 1);

    if (c < CONVD) {
        float acc = cb[c];
#pragma unroll
        for (int j = 0; j < 4; ++j) {
            int lj = l - 3 + j;
            if (lj >= 0)
                acc = fmaf(cw[c * 4 + j],
                           g_zx[(size_t)(tokidx - 3 + j) * DIN + DINNER + c], acc);
        }
        acc = acc / (1.f + expf(-acc));
        g_xbc[(size_t)tokidx * CONVD + c] = acc;
    } else {
        int h = c - CONVD;
        float raw = g_zx[(size_t)tokidx * DIN + (DINNER + CONVD) + h] + dtb[h];
        float sp  = (raw > 15.f) ? raw : log1pf(expf(raw));
        g_dts[(size_t)tokidx * NHEADS + h] = sp;
        g_dAs[(size_t)tokidx * NHEADS + h] = expf(sp * (-expf(Alog[h])));
    }
}

// ================= Kernel 4: selective scan (R12 monolithic, FROZEN) =====
__global__ void __launch_bounds__(256, 1) k_scan()
{
    int blk  = blockIdx.x;
    int b    = blk >> 6;
    int rem  = blk & 63;
    int h    = rem >> 1;
    int nh   = rem & 1;
    int tid  = threadIdx.x;
    int pp = tid >> 3;
    int q  = tid & 7;
    int p0 = pp * 2;

    __shared__ __align__(16) float xs[2][8][64];
    __shared__ __align__(16) float Bh[2][8][64];
    __shared__ __align__(16) float Ch[2][8][64];
    __shared__ float sdt[SEQLEN], sdA[SEQLEN];

    for (int t = tid; t < SEQLEN; t += 256) {
        sdt[t] = g_dts[(size_t)(b * SEQLEN + t) * NHEADS + h];
        sdA[t] = g_dAs[(size_t)(b * SEQLEN + t) * NHEADS + h];
    }

    float s0[8], s1[8];
#pragma unroll
    for (int j = 0; j < 8; ++j) { s0[j] = 0.f; s1[j] = 0.f; }

    float* yout = nh ? g_y1 : g_y0;
    const float* base = g_xbc + (size_t)(b * SEQLEN) * CONVD;

    int off = -1;
    if (tid < 64)        off = h * HEADD + tid;
    else if (tid < 128)  off = DINNER + nh * 64 + (tid - 64);
    else if (tid < 192)  off = DINNER + DSTATE + nh * 64 + (tid - 128);
    bool stager = (off >= 0);

    float pre[8];
    if (stager) {
#pragma unroll
        for (int j = 0; j < 8; ++j)
            pre[j] = base[(size_t)j * CONVD + off];
    }

    float* youtbase = yout + ((size_t)(b * SEQLEN) * NHEADS + h) * HEADD + p0;

    for (int tg = 0; tg < SEQLEN / 8; ++tg) {
        int set = tg & 1;
        if (stager) {
            if (tid < 64) {
#pragma unroll
                for (int j = 0; j < 8; ++j) xs[set][j][tid] = pre[j];
            } else if (tid < 128) {
#pragma unroll
                for (int j = 0; j < 8; ++j) Bh[set][j][tid - 64] = pre[j];
            } else {
#pragma unroll
                for (int j = 0; j < 8; ++j) Ch[set][j][tid - 128] = pre[j];
            }
        }
        __syncthreads();
        if (stager && tg + 1 < SEQLEN / 8) {
#pragma unroll
            for (int j = 0; j < 8; ++j)
                pre[j] = base[(size_t)((tg + 1) * 8 + j) * CONVD + off];
        }

#pragma unroll
        for (int u = 0; u < 8; ++u) {
            int t = tg * 8 + u;
            float dtv = sdt[t], dAv = sdA[t];
            float2 xv = *(const float2*)&xs[set][u][p0];
            float xd0 = xv.x * dtv, xd1 = xv.y * dtv;
            float4 Bv0 = *(const float4*)&Bh[set][u][q * 8];
            float4 Bv1 = *(const float4*)&Bh[set][u][q * 8 + 4];
            float4 Cv0 = *(const float4*)&Ch[set][u][q * 8];
            float4 Cv1 = *(const float4*)&Ch[set][u][q * 8 + 4];

            float y0 = 0.f, y1 = 0.f;
#define STEPN(j, bv, cv)                                           \
            s0[j] = fmaf(s0[j], dAv, xd0 * (bv));                  \
            y0    = fmaf(s0[j], (cv), y0);                         \
            s1[j] = fmaf(s1[j], dAv, xd1 * (bv));                  \
            y1    = fmaf(s1[j], (cv), y1);
            STEPN(0, Bv0.x, Cv0.x)
            STEPN(1, Bv0.y, Cv0.y)
            STEPN(2, Bv0.z, Cv0.z)
            STEPN(3, Bv0.w, Cv0.w)
            STEPN(4, Bv1.x, Cv1.x)
            STEPN(5, Bv1.y, Cv1.y)
            STEPN(6, Bv1.z, Cv1.z)
            STEPN(7, Bv1.w, Cv1.w)
#undef STEPN
            y0 += __shfl_xor_sync(0xffffffffu, y0, 1);
            y1 += __shfl_xor_sync(0xffffffffu, y1, 1);
            y0 += __shfl_xor_sync(0xffffffffu, y0, 2);
            y1 += __shfl_xor_sync(0xffffffffu, y1, 2);
            y0 += __shfl_xor_sync(0xffffffffu, y0, 4);
            y1 += __shfl_xor_sync(0xffffffffu, y1, 4);
            if (q == 0)
                *(float2*)&youtbase[(size_t)t * DINNER] = make_float2(y0, y1);
        }
    }
}

// ================= Kernel 5: gating + RMSNorm (float4 loads) =============
__global__ void __launch_bounds__(256) k_gatenorm(const float* __restrict__ Dv,
                                                  const float* __restrict__ nw)
{
    int tok = blockIdx.x;
    int tid = threadIdx.x;
    __shared__ float4 gsh[DINNER / 4];
    __shared__ float red[8];
    __shared__ float scale_s;

    float ss = 0.f;
#pragma unroll
    for (int k = 0; k < 2; ++k) {
        int qd = tid + k * 256;             // quad index 0..511
        int i  = qd * 4;
        float dh = Dv[i >> 6];              // 4-aligned quad stays in one head
        float4 x  = *(const float4*)&g_xbc[(size_t)tok * CONVD + i];
        float4 y0 = *(const float4*)&g_y0[(size_t)tok * DINNER + i];
        float4 y1 = *(const float4*)&g_y1[(size_t)tok * DINNER + i];
        float4 z  = *(const float4*)&g_zx[(size_t)tok * DIN + i];
        float4 g;
        g.x = (y0.x + y1.x + dh * x.x) * (z.x / (1.f + expf(-z.x)));
        g.y = (y0.y + y1.y + dh * x.y) * (z.y / (1.f + expf(-z.y)));
        g.z = (y0.z + y1.z + dh * x.z) * (z.z / (1.f + expf(-z.z)));
        g.w = (y0.w + y1.w + dh * x.w) * (z.w / (1.f + expf(-z.w)));
        gsh[qd] = g;
        ss += g.x * g.x + g.y * g.y + g.z * g.z + g.w * g.w;
    }
#pragma unroll
    for (int o = 16; o; o >>= 1) ss += __shfl_xor_sync(0xffffffffu, ss, o);
    if ((tid & 31) == 0) red[tid >> 5] = ss;
    __syncthreads();
    if (tid == 0) {
        float tot = 0.f;
#pragma unroll
        for (int w = 0; w < 8; ++w) tot += red[w];
        scale_s = rsqrtf(tot / (float)DINNER + 1e-5f);
    }
    __syncthreads();
    float sc = scale_s;
#pragma unroll
    for (int k = 0; k < 2; ++k) {
        int qd = tid + k * 256;
        int i  = qd * 4;
        float4 g = gsh[qd];
        float4 w = *(const float4*)&nw[i];
        float4 o;
        o.x = g.x * sc * w.x; o.y = g.y * sc * w.y;
        o.z = g.z * sc * w.z; o.w = g.w * sc * w.w;
        *(float4*)&g_hn[(size_t)tok * DINNER + i] = o;
    }
}

// ================= Kernel 6: classifier GEMM (warp K-split) ==============
__global__ void __launch_bounds__(256) k_cls(const float* __restrict__ Wc,
                                             const float* __restrict__ bc,
                                             float* __restrict__ out)
{
    __shared__ float Ws[CLS_KT * CLS_WPAD];
    __shared__ float Hs[CLS_TOK * CLS_KT];

    const int tok0 = blockIdx.x * CLS_TOK;
    const int tid  = threadIdx.x;
    const int tg = tid >> 7;
    const int qg = (tid >> 5) & 3;
    const int kg = tid & 31;

    float acc[4][12];
#pragma unroll
    for (int t = 0; t < 4; ++t)
#pragma unroll
        for (int j = 0; j < 12; ++j) acc[t][j] = 0.f;

    for (int k0 = 0; k0 < DINNER; k0 += CLS_KT) {
#pragma unroll
        for (int r = 0; r < 24; ++r) {
            int idx = tid + r * 256;
            int kk = idx / 48, c = idx - kk * 48;
            Ws[kk * CLS_WPAD + c] = Wc[(size_t)(k0 + kk) * NCLS + c];
        }
#pragma unroll
        for (int r = 0; r < 4; ++r) {
            int idx = tid + r * 256;
            int tt = idx >> 7, kk = idx & 127;
            Hs[tt * CLS_KT + kk] = g_hn[(size_t)(tok0 + tt) * DINNER + k0 + kk];
        }
        __syncthreads();

#pragma unroll
        for (int i = 0; i < 4; ++i) {
            int kk = i * 32 + kg;
            float hv[4];
#pragma unroll
            for (int t = 0; t < 4; ++t)
                hv[t] = Hs[(tg * 4 + t) * CLS_KT + kk];
            const float* wr = &Ws[kk * CLS_WPAD + qg * 12];
            float4 w0 = *(const float4*)(wr);
            float4 w1 = *(const float4*)(wr + 4);
            float4 w2 = *(const float4*)(wr + 8);
#pragma unroll
            for (int t = 0; t < 4; ++t) {
                acc[t][0]  = fmaf(hv[t], w0.x, acc[t][0]);
                acc[t][1]  = fmaf(hv[t], w0.y, acc[t][1]);
                acc[t][2]  = fmaf(hv[t], w0.z, acc[t][2]);
                acc[t][3]  = fmaf(hv[t], w0.w, acc[t][3]);
                acc[t][4]  = fmaf(hv[t], w1.x, acc[t][4]);
                acc[t][5]  = fmaf(hv[t], w1.y, acc[t][5]);
                acc[t][6]  = fmaf(hv[t], w1.z, acc[t][6]);
                acc[t][7]  = fmaf(hv[t], w1.w, acc[t][7]);
                acc[t][8]  = fmaf(hv[t], w2.x, acc[t][8]);
                acc[t][9]  = fmaf(hv[t], w2.y, acc[t][9]);
                acc[t][10] = fmaf(hv[t], w2.z, acc[t][10]);
                acc[t][11] = fmaf(hv[t], w2.w, acc[t][11]);
            }
        }
        __syncthreads();
    }

#pragma unroll
    for (int offw = 16; offw; offw >>= 1)
#pragma unroll
        for (int t = 0; t < 4; ++t)
#pragma unroll
            for (int j = 0; j < 12; ++j)
                acc[t][j] += __shfl_down_sync(0xffffffffu, acc[t][j], offw);

    if (kg == 0) {
#pragma unroll
        for (int t = 0; t < 4; ++t) {
            int tok = tok0 + tg * 4 + t;
            float* op = &out[(size_t)tok * NCLS + qg * 12];
#pragma unroll
            for (int j = 0; j < 12; ++j)
                op[j] = acc[t][j] + bc[qg * 12 + j];
        }
    }
}

// ================= launcher (R14 schedule) =================
extern "C" void kernel_launch(void* const* d_in, const int* in_sizes, int n_in,
                              void* d_out, int out_size)
{
    const float* inputs  = (const float*)d_in[0];
    const float* W_in    = (const float*)d_in[1];
    const float* conv_w  = (const float*)d_in[2];
    const float* conv_b  = (const float*)d_in[3];
    const float* dt_bias = (const float*)d_in[4];
    const float* A_log   = (const float*)d_in[5];
    const float* Dv      = (const float*)d_in[6];
    const float* norm_w  = (const float*)d_in[7];
    const float* W_cls   = (const float*)d_in[9];
    const float* b_cls   = (const float*)d_in[10];
    float* out = (float*)d_out;

    (void)in_sizes; (void)n_in; (void)out_size;

    static cudaStream_t s2 = nullptr;
    static cudaEvent_t ev1 = nullptr, ev2 = nullptr;
    static bool init_done = false;
    if (!init_done) {
        cudaFuncSetAttribute(k_gemm_mma,
                             cudaFuncAttributeMaxDynamicSharedMemorySize,
                             GEMM_SMEM);
        int prio_lo = 0, prio_hi = 0;
        cudaDeviceGetStreamPriorityRange(&prio_lo, &prio_hi);
        cudaStreamCreateWithPriority(&s2, cudaStreamNonBlocking, prio_lo);
        cudaEventCreateWithFlags(&ev1, cudaEventDisableTiming);
        cudaEventCreateWithFlags(&ev2, cudaEventDisableTiming);
        init_done = true;
    }

    // stream 0: conversions, then xBC/dt column tiles of the GEMM
    k_cvt<<<1024 + 1120, 256>>>(inputs, W_in);
    {
        dim3 grid(19, NTOK / 128);           // col tiles 16..34 (cols 2048..4479)
        k_gemm_mma<<<grid, 256, GEMM_SMEM>>>(16);
    }
    // conv on the critical path (coalesced reads; feeds the scan)
    {
        int tot = NTOK * (CONVD + NHEADS);
        k_conv<<<(tot + 255) / 256, 256>>>(conv_w, conv_b, dt_bias, A_log);
    }
    // fork AFTER conv: z-column GEMM (low priority) hides under the scan
    cudaEventRecord(ev1, 0);
    cudaStreamWaitEvent(s2, ev1, 0);
    {
        dim3 grid(16, NTOK / 128);           // col tiles 0..15 (z, cols 0..2047)
        k_gemm_mma<<<grid, 256, GEMM_SMEM, s2>>>(0);
    }
    cudaEventRecord(ev2, s2);

    // stream 0: scan (frozen R12 body)
    k_scan<<<128, 256>>>();

    // join: gatenorm needs z (s2 gemm)
    cudaStreamWaitEvent(0, ev2, 0);
    k_gatenorm<<<NTOK, 256>>>(Dv, norm_w);
    k_cls<<<NTOK / CLS_TOK, 256>>>(W_cls, b_cls, out);
}